// round 13
// baseline (speedup 1.0000x reference)
#include <cuda_runtime.h>
#include <cuda_fp16.h>
#include <cstdint>

#define N_TOK 8192
#define DIM   2048
#define MID   512
#define NEXP  4

#define BM 128
#define BN 64
#define KC 64                        // fp16 K elems per chunk (128 B rows)
#define A_TILE_B (128 * 128)         // 16 KB
#define B_TILE_B (64 * 128)          // 8 KB
#define OFF_A 0
#define OFF_B A_TILE_B
#define STAGE_B (A_TILE_B + B_TILE_B)   // 24 KB
#define NSTAGE 3
#define SMEM_TOT (NSTAGE * STAGE_B)  // 72 KB

// ---------------- device scratch ----------------
__device__ int g_counts[NEXP];
__device__ int g_idx[NEXP * N_TOK];
__device__ int g_is64;
__device__ __half g_x[(size_t)N_TOK * DIM];
__device__ __half g_w1[(size_t)NEXP * MID * DIM];
__device__ __half g_w2[(size_t)NEXP * DIM * MID];
__device__ __half g_h[(size_t)N_TOK * MID];

// ---------------- helpers ----------------
__device__ __forceinline__ uint32_t smem_u32(const void* p) {
    uint32_t a;
    asm("{ .reg .u64 t; cvta.to.shared.u64 t, %1; cvt.u32.u64 %0, t; }" : "=r"(a) : "l"(p));
    return a;
}
__device__ __forceinline__ void ldm_x4(uint32_t* r, uint32_t addr) {
    asm volatile("ldmatrix.sync.aligned.m8n8.x4.shared.b16 {%0,%1,%2,%3}, [%4];"
                 : "=r"(r[0]), "=r"(r[1]), "=r"(r[2]), "=r"(r[3]) : "r"(addr));
}
__device__ __forceinline__ void mma16816h(float* c, const uint32_t* a, uint32_t b0, uint32_t b1) {
    asm volatile("mma.sync.aligned.m16n8k16.row.col.f32.f16.f16.f32 "
                 "{%0,%1,%2,%3}, {%4,%5,%6,%7}, {%8,%9}, {%0,%1,%2,%3};"
                 : "+f"(c[0]), "+f"(c[1]), "+f"(c[2]), "+f"(c[3])
                 : "r"(a[0]), "r"(a[1]), "r"(a[2]), "r"(a[3]), "r"(b0), "r"(b1));
}
#define CP_ASYNC16(dst, src) \
    asm volatile("cp.async.cg.shared.global [%0], [%1], 16;" :: "r"(dst), "l"(src))
#define CP_ASYNC16_Z(dst, src, zb) \
    asm volatile("cp.async.cg.shared.global [%0], [%1], 16, %2;" :: "r"(dst), "l"(src), "r"(zb))
#define CP_COMMIT() asm volatile("cp.async.commit_group;" ::: "memory")
#define CP_WAIT1()  asm volatile("cp.async.wait_group 1;" ::: "memory")
#define CP_WAIT0()  asm volatile("cp.async.wait_group 0;" ::: "memory")

// ---------------- setup kernels ----------------
__global__ void setup_kernel(const int* __restrict__ dom32) {
    if (threadIdx.x < NEXP) g_counts[threadIdx.x] = 0;
    if (threadIdx.x == 0) {
        int odd_zero = 1;
        for (int i = 1; i < 512; i += 2)
            if (dom32[i] != 0) { odd_zero = 0; break; }
        g_is64 = odd_zero;
    }
}

__global__ void bucket_kernel(const void* __restrict__ dom) {
    int n = blockIdx.x * blockDim.x + threadIdx.x;
    if (n >= N_TOK) return;
    int e = g_is64 ? (int)((const long long*)dom)[n] : ((const int*)dom)[n];
    int p = atomicAdd(&g_counts[e], 1);
    g_idx[e * N_TOK + p] = n;
}

// fused fp32 -> fp16 for x, W1, W2; 2 independent float4 per iteration (MLP=2)
#define NX4  ((N_TOK * DIM) / 4)
#define NW14 ((NEXP * MID * DIM) / 4)
#define NW24 ((NEXP * DIM * MID) / 4)
#define NTOT4 (NX4 + NW14 + NW24)
__device__ __forceinline__ void cvt_one(const float4* __restrict__ s4,
                                        uint2* __restrict__ d2, int j) {
    float4 v = s4[j];
    __half2 a(__float2half_rn(v.x), __float2half_rn(v.y));
    __half2 b(__float2half_rn(v.z), __float2half_rn(v.w));
    d2[j] = make_uint2(*reinterpret_cast<uint32_t*>(&a),
                       *reinterpret_cast<uint32_t*>(&b));
}
__global__ void cvt_all_kernel(const float* __restrict__ x,
                               const float* __restrict__ w1,
                               const float* __restrict__ w2,
                               __half* __restrict__ xd,
                               __half* __restrict__ w1d,
                               __half* __restrict__ w2d) {
    const int tidg = blockIdx.x * blockDim.x + threadIdx.x;
    const int stride = gridDim.x * blockDim.x;
    auto resolve = [&](int i, const float4*& s4, uint2*& d2, int& j) {
        if (i < NX4)              { s4 = (const float4*)x;  d2 = (uint2*)xd;  j = i; }
        else if (i < NX4 + NW14)  { s4 = (const float4*)w1; d2 = (uint2*)w1d; j = i - NX4; }
        else                      { s4 = (const float4*)w2; d2 = (uint2*)w2d; j = i - NX4 - NW14; }
    };
    int i = tidg;
    for (; i + stride < NTOT4; i += 2 * stride) {
        const float4 *sa, *sb; uint2 *da, *db; int ja, jb2;
        resolve(i, sa, da, ja);
        resolve(i + stride, sb, db, jb2);
        float4 va = sa[ja];
        float4 vb = sb[jb2];
        __half2 a0(__float2half_rn(va.x), __float2half_rn(va.y));
        __half2 a1(__float2half_rn(va.z), __float2half_rn(va.w));
        __half2 b0(__float2half_rn(vb.x), __float2half_rn(vb.y));
        __half2 b1(__float2half_rn(vb.z), __float2half_rn(vb.w));
        da[ja]  = make_uint2(*reinterpret_cast<uint32_t*>(&a0), *reinterpret_cast<uint32_t*>(&a1));
        db[jb2] = make_uint2(*reinterpret_cast<uint32_t*>(&b0), *reinterpret_cast<uint32_t*>(&b1));
    }
    if (i < NTOT4) {
        const float4* s4; uint2* d2; int j;
        resolve(i, s4, d2, j);
        cvt_one(s4, d2, j);
    }
}

// ---------------- grouped GEMM: 3-stage cp.async + single-term fp16 mma ----------------
// BM=128 x BN=64; 8 warps 4(m) x 2(n); warp tile 32x32; 3 CTAs/SM.
template <int KDIM, bool IS_G1>
__global__ __launch_bounds__(256, 3)
void moe_gemm_kernel(const float* __restrict__ x,
                     const __half* __restrict__ A_h,
                     const __half* __restrict__ B_h,
                     const float* __restrict__ bias,
                     float* __restrict__ out) {
    constexpr int NCH   = KDIM / KC;
    constexpr int NCOLS = IS_G1 ? MID : DIM;

    const int tiles_per_e = N_TOK / BM;            // 64
    const int e     = blockIdx.x / tiles_per_e;
    const int mtile = blockIdx.x % tiles_per_e;
    const int ntile = blockIdx.y;

    const int cnt  = g_counts[e];
    const int row0 = mtile * BM;
    if (row0 >= cnt) return;
    const int* __restrict__ idx = g_idx + e * N_TOK;

    extern __shared__ char smem[];
    const uint32_t sbase = smem_u32(smem);

    const int tid = threadIdx.x;
    const int wid = tid >> 5;
    const int lid = tid & 31;
    const int mrow0 = (wid & 3) * 32;
    const int ncol0 = (wid >> 2) * 32;

    // ---- cp.async fill mapping: 128 B rows = 8 x 16 B chunks; 256 threads.
    // A: 128 rows -> 4 per thread; B: 64 rows -> 2 per thread.
    const int c8 = tid & 7;
    const __half* ahp[4];
    uint32_t zbA[4];
    uint32_t stsA[4];
#pragma unroll
    for (int i = 0; i < 4; i++) {
        const int row = (tid >> 3) + 32 * i;
        const int grow = row0 + row;
        const bool live = (grow < cnt);
        ahp[i] = live ? A_h + (size_t)idx[grow] * KDIM + c8 * 8 : A_h;
        zbA[i] = live ? 16u : 0u;
        stsA[i] = (uint32_t)(row * 128 + ((c8 ^ (row & 7)) << 4));
    }
    const __half* bpp[2];
    uint32_t stsB[2];
#pragma unroll
    for (int i = 0; i < 2; i++) {
        const int row = (tid >> 3) + 32 * i;   // 0..63
        bpp[i] = B_h + ((size_t)e * NCOLS + (size_t)ntile * BN + row) * KDIM + c8 * 8;
        stsB[i] = (uint32_t)(row * 128 + ((c8 ^ (row & 7)) << 4));
    }

    auto issue = [&](int ch, int slot) {
        const int k0 = ch * KC;
        const uint32_t st = sbase + (uint32_t)(slot * STAGE_B);
#pragma unroll
        for (int i = 0; i < 4; i++)
            CP_ASYNC16_Z(st + OFF_A + stsA[i], ahp[i] + k0, zbA[i]);
#pragma unroll
        for (int i = 0; i < 2; i++)
            CP_ASYNC16(st + OFF_B + stsB[i], bpp[i] + k0);
        CP_COMMIT();
    };

    float acc[2][4][4];
#pragma unroll
    for (int mi = 0; mi < 2; mi++)
#pragma unroll
        for (int nj = 0; nj < 4; nj++)
#pragma unroll
            for (int q = 0; q < 4; q++) acc[mi][nj][q] = 0.f;

    // ---- ldmatrix per-lane addresses (128 B rows, mask = row&7) ----
    uint32_t aRow[2], aMsk[2];
#pragma unroll
    for (int mi = 0; mi < 2; mi++) {
        const int r = mrow0 + mi * 16 + (lid & 15);
        aRow[mi] = (uint32_t)(r * 128);
        aMsk[mi] = (uint32_t)(r & 7);
    }
    const uint32_t ja = (uint32_t)(lid >> 4);
    uint32_t bRow[2], bMsk[2];
#pragma unroll
    for (int h2 = 0; h2 < 2; h2++) {
        const int r = ncol0 + h2 * 16 + (lid & 7) + 8 * (lid >> 4);
        bRow[h2] = (uint32_t)(r * 128);
        bMsk[h2] = (uint32_t)(r & 7);
    }
    const uint32_t jb = (uint32_t)((lid >> 3) & 1);

    issue(0, 0);
    issue(1, 1);

    int slot = 0;                       // slot of chunk kc
    for (int kc = 0; kc < NCH; kc++) {
        CP_WAIT1();                     // this thread's copies for chunk kc done
        __syncthreads();                // all threads' waits done -> tile visible; slot reusable
        if (kc + 2 < NCH) {
            int s2 = slot + 2;
            if (s2 >= NSTAGE) s2 -= NSTAGE;
            issue(kc + 2, s2);
        } else {
            CP_COMMIT();                // uniform group accounting
        }

        const uint32_t sa = sbase + (uint32_t)(slot * STAGE_B);
#pragma unroll
        for (int ks = 0; ks < 4; ks++) {
            uint32_t ah[2][4], bf[2][4];
#pragma unroll
            for (int mi = 0; mi < 2; mi++) {
                const uint32_t adr = sa + aRow[mi] + ((((uint32_t)(2 * ks) + ja) ^ aMsk[mi]) << 4);
                ldm_x4(ah[mi], adr + OFF_A);
            }
#pragma unroll
            for (int h2 = 0; h2 < 2; h2++) {
                const uint32_t adr = sa + bRow[h2] + ((((uint32_t)(2 * ks) + jb) ^ bMsk[h2]) << 4);
                ldm_x4(bf[h2], adr + OFF_B);
            }
#pragma unroll
            for (int mi = 0; mi < 2; mi++)
#pragma unroll
                for (int nj = 0; nj < 4; nj++) {
                    const int h2 = nj >> 1, sl = nj & 1;
                    mma16816h(acc[mi][nj], ah[mi], bf[h2][2 * sl], bf[h2][2 * sl + 1]);
                }
        }
        if (++slot == NSTAGE) slot = 0;
    }
    CP_WAIT0();

    // ---- epilogue ----
    const int lr = lid >> 2;
    const int c2 = (lid & 3) * 2;
    const float* __restrict__ bb = bias + (size_t)e * NCOLS + (size_t)ntile * BN;

#pragma unroll
    for (int mi = 0; mi < 2; mi++) {
#pragma unroll
        for (int half = 0; half < 2; half++) {
            const int rloc = mrow0 + mi * 16 + lr + half * 8;
            const int grow = row0 + rloc;
            if (grow < cnt) {
                const long long tok = idx[grow];
#pragma unroll
                for (int nj = 0; nj < 4; nj++) {
                    const int col = ncol0 + nj * 8 + c2;
                    const float v0 = acc[mi][nj][half * 2 + 0];
                    const float v1 = acc[mi][nj][half * 2 + 1];
                    if (IS_G1) {
                        float r0 = v0 + bb[col];
                        float r1 = v1 + bb[col + 1];
                        r0 = r0 > 0.f ? r0 : 0.f;
                        r1 = r1 > 0.f ? r1 : 0.f;
                        __half2 hv(__float2half_rn(r0), __float2half_rn(r1));
                        *(uint32_t*)(g_h + (size_t)tok * MID + (size_t)ntile * BN + col) =
                            *reinterpret_cast<uint32_t*>(&hv);
                    } else {
                        const size_t o = (size_t)tok * DIM + (size_t)ntile * BN + col;
                        float2 xv = *(const float2*)(x + o);
                        *(float2*)(out + o) =
                            make_float2(xv.x + v0 + bb[col], xv.y + v1 + bb[col + 1]);
                    }
                }
            }
        }
    }
}

// ---------------- host launch ----------------
extern "C" void kernel_launch(void* const* d_in, const int* in_sizes, int n_in,
                              void* d_out, int out_size) {
    const float* x       = (const float*)d_in[0];
    const void*  domains = d_in[1];
    const float* W1      = (const float*)d_in[2];
    const float* b1      = (const float*)d_in[3];
    const float* W2      = (const float*)d_in[4];
    const float* b2      = (const float*)d_in[5];
    float*       out     = (float*)d_out;

    setup_kernel<<<1, 32>>>((const int*)domains);
    bucket_kernel<<<(N_TOK + 255) / 256, 256>>>(domains);

    __half *xh, *w1h, *w2h, *hh;
    cudaGetSymbolAddress((void**)&xh,  g_x);
    cudaGetSymbolAddress((void**)&w1h, g_w1);
    cudaGetSymbolAddress((void**)&w2h, g_w2);
    cudaGetSymbolAddress((void**)&hh,  g_h);

    cvt_all_kernel<<<2048, 256>>>(x, W1, W2, xh, w1h, w2h);

    cudaFuncSetAttribute(moe_gemm_kernel<DIM, true>,
                         cudaFuncAttributeMaxDynamicSharedMemorySize, SMEM_TOT);
    cudaFuncSetAttribute(moe_gemm_kernel<MID, false>,
                         cudaFuncAttributeMaxDynamicSharedMemorySize, SMEM_TOT);

    dim3 grid1(NEXP * (N_TOK / BM), MID / BN);   // (256, 8)
    moe_gemm_kernel<DIM, true><<<grid1, 256, SMEM_TOT>>>(x, xh, w1h, b1, nullptr);

    dim3 grid2(NEXP * (N_TOK / BM), DIM / BN);   // (256, 32)
    moe_gemm_kernel<MID, false><<<grid2, 256, SMEM_TOT>>>(x, hh, w2h, b2, out);
}

// round 14
// speedup vs baseline: 1.1919x; 1.1919x over previous
#include <cuda_runtime.h>
#include <cuda_fp16.h>
#include <cstdint>

#define N_TOK 8192
#define DIM   2048
#define MID   512
#define NEXP  4

#define BM 128
#define BN 128
#define KC 64                        // fp16 K elems per chunk (128 B rows)
#define A_TILE_B (128 * 128)         // 16 KB
#define B_TILE_B (128 * 128)         // 16 KB
#define OFF_A 0
#define OFF_B A_TILE_B
#define STAGE_B (A_TILE_B + B_TILE_B)   // 32 KB
#define NSTAGE 3
#define SMEM_TOT (NSTAGE * STAGE_B)  // 96 KB

// ---------------- device scratch ----------------
__device__ int g_counts[NEXP];
__device__ int g_idx[NEXP * N_TOK];
__device__ int g_is64;
__device__ __half g_x[(size_t)N_TOK * DIM];
__device__ __half g_w1[(size_t)NEXP * MID * DIM];
__device__ __half g_w2[(size_t)NEXP * DIM * MID];
__device__ __half g_h[(size_t)N_TOK * MID];

// ---------------- helpers ----------------
__device__ __forceinline__ uint32_t smem_u32(const void* p) {
    uint32_t a;
    asm("{ .reg .u64 t; cvta.to.shared.u64 t, %1; cvt.u32.u64 %0, t; }" : "=r"(a) : "l"(p));
    return a;
}
__device__ __forceinline__ void ldm_x4(uint32_t* r, uint32_t addr) {
    asm volatile("ldmatrix.sync.aligned.m8n8.x4.shared.b16 {%0,%1,%2,%3}, [%4];"
                 : "=r"(r[0]), "=r"(r[1]), "=r"(r[2]), "=r"(r[3]) : "r"(addr));
}
__device__ __forceinline__ void mma16816h(float* c, const uint32_t* a, uint32_t b0, uint32_t b1) {
    asm volatile("mma.sync.aligned.m16n8k16.row.col.f32.f16.f16.f32 "
                 "{%0,%1,%2,%3}, {%4,%5,%6,%7}, {%8,%9}, {%0,%1,%2,%3};"
                 : "+f"(c[0]), "+f"(c[1]), "+f"(c[2]), "+f"(c[3])
                 : "r"(a[0]), "r"(a[1]), "r"(a[2]), "r"(a[3]), "r"(b0), "r"(b1));
}
#define CP_ASYNC16(dst, src) \
    asm volatile("cp.async.cg.shared.global [%0], [%1], 16;" :: "r"(dst), "l"(src))
#define CP_ASYNC16_Z(dst, src, zb) \
    asm volatile("cp.async.cg.shared.global [%0], [%1], 16, %2;" :: "r"(dst), "l"(src), "r"(zb))
#define CP_COMMIT() asm volatile("cp.async.commit_group;" ::: "memory")
#define CP_WAIT1()  asm volatile("cp.async.wait_group 1;" ::: "memory")
#define CP_WAIT0()  asm volatile("cp.async.wait_group 0;" ::: "memory")

// ---------------- setup ----------------
__global__ void setup_kernel(const int* __restrict__ dom32) {
    if (threadIdx.x < NEXP) g_counts[threadIdx.x] = 0;
    if (threadIdx.x == 0) {
        int odd_zero = 1;
        for (int i = 1; i < 512; i += 2)
            if (dom32[i] != 0) { odd_zero = 0; break; }
        g_is64 = odd_zero;
    }
}

// fused: bucket (first 32 blocks) + fp32->fp16 cvt of x and W1 (all blocks, MLP=2)
#define NX4  ((N_TOK * DIM) / 4)
#define NW14 ((NEXP * MID * DIM) / 4)
#define NCVT4 (NX4 + NW14)
#define NW24 ((NEXP * DIM * MID) / 4)
__global__ void prep_kernel(const void* __restrict__ dom,
                            const float* __restrict__ x,
                            const float* __restrict__ w1,
                            __half* __restrict__ xd,
                            __half* __restrict__ w1d) {
    // bucket: first 32 blocks cover all 8192 tokens
    if (blockIdx.x < 32) {
        const int n = blockIdx.x * 256 + threadIdx.x;
        int e = g_is64 ? (int)((const long long*)dom)[n] : ((const int*)dom)[n];
        int p = atomicAdd(&g_counts[e], 1);
        g_idx[e * N_TOK + p] = n;
    }
    // cvt x + W1
    const int tidg = blockIdx.x * blockDim.x + threadIdx.x;
    const int stride = gridDim.x * blockDim.x;
    auto resolve = [&](int i, const float4*& s4, uint2*& d2, int& j) {
        if (i < NX4) { s4 = (const float4*)x;  d2 = (uint2*)xd;  j = i; }
        else         { s4 = (const float4*)w1; d2 = (uint2*)w1d; j = i - NX4; }
    };
    int i = tidg;
    for (; i + stride < NCVT4; i += 2 * stride) {
        const float4 *sa, *sb; uint2 *da, *db; int ja, jb2;
        resolve(i, sa, da, ja);
        resolve(i + stride, sb, db, jb2);
        float4 va = sa[ja];
        float4 vb = sb[jb2];
        __half2 a0(__float2half_rn(va.x), __float2half_rn(va.y));
        __half2 a1(__float2half_rn(va.z), __float2half_rn(va.w));
        __half2 b0(__float2half_rn(vb.x), __float2half_rn(vb.y));
        __half2 b1(__float2half_rn(vb.z), __float2half_rn(vb.w));
        da[ja]  = make_uint2(*reinterpret_cast<uint32_t*>(&a0), *reinterpret_cast<uint32_t*>(&a1));
        db[jb2] = make_uint2(*reinterpret_cast<uint32_t*>(&b0), *reinterpret_cast<uint32_t*>(&b1));
    }
    if (i < NCVT4) {
        const float4* s4; uint2* d2; int j;
        resolve(i, s4, d2, j);
        float4 v = s4[j];
        __half2 a(__float2half_rn(v.x), __float2half_rn(v.y));
        __half2 b(__float2half_rn(v.z), __float2half_rn(v.w));
        d2[j] = make_uint2(*reinterpret_cast<uint32_t*>(&a),
                           *reinterpret_cast<uint32_t*>(&b));
    }
}

// ---------------- grouped GEMM: 3-stage cp.async + single-term fp16 mma ----------------
// BM=128 x BN=128; 8 warps 4(m) x 2(n); warp tile 32x64; 2 CTAs/SM. (R12-proven loop.)
// gemm1 additionally carries a cvt slab: blockIdx.y == MID/BN converts W2 -> w2h
// (overlaps DRAM-bound cvt with tensor-bound GEMM; gemm2 sees w2h after this kernel).
template <int KDIM, bool IS_G1>
__global__ __launch_bounds__(256, 2)
void moe_gemm_kernel(const float* __restrict__ x,
                     const __half* __restrict__ A_h,
                     const __half* __restrict__ B_h,
                     const float* __restrict__ bias,
                     float* __restrict__ out,
                     const float* __restrict__ w2_src,
                     __half* __restrict__ w2_dst) {
    constexpr int NCH   = KDIM / KC;
    constexpr int NCOLS = IS_G1 ? MID : DIM;

    if (IS_G1 && blockIdx.y == (MID / BN)) {
        // W2 conversion slab: 256 blocks, grid-stride over NW24 float4
        int i = blockIdx.x * blockDim.x + threadIdx.x;
        const int stride = 256 * 256;
        const float4* s4 = (const float4*)w2_src;
        uint2* d2 = (uint2*)w2_dst;
        for (; i < NW24; i += stride) {
            float4 v = s4[i];
            __half2 a(__float2half_rn(v.x), __float2half_rn(v.y));
            __half2 b(__float2half_rn(v.z), __float2half_rn(v.w));
            d2[i] = make_uint2(*reinterpret_cast<uint32_t*>(&a),
                               *reinterpret_cast<uint32_t*>(&b));
        }
        return;
    }

    const int tiles_per_e = N_TOK / BM;            // 64
    const int e     = blockIdx.x / tiles_per_e;
    const int mtile = blockIdx.x % tiles_per_e;
    const int ntile = blockIdx.y;

    const int cnt  = g_counts[e];
    const int row0 = mtile * BM;
    if (row0 >= cnt) return;
    const int* __restrict__ idx = g_idx + e * N_TOK;

    extern __shared__ char smem[];
    const uint32_t sbase = smem_u32(smem);

    const int tid = threadIdx.x;
    const int wid = tid >> 5;
    const int lid = tid & 31;
    const int mrow0 = (wid & 3) * 32;
    const int ncol0 = (wid >> 2) * 64;

    // ---- cp.async fill mapping: 128 B rows = 8 x 16 B chunks; 256 threads.
    const int c8 = tid & 7;
    const __half* ahp[4];
    const __half* bpp[4];
    uint32_t zbA[4];
    uint32_t sts[4];
#pragma unroll
    for (int i = 0; i < 4; i++) {
        const int row = (tid >> 3) + 32 * i;
        const int grow = row0 + row;
        const bool live = (grow < cnt);
        ahp[i] = live ? A_h + (size_t)idx[grow] * KDIM + c8 * 8 : A_h;
        zbA[i] = live ? 16u : 0u;
        bpp[i] = B_h + ((size_t)e * NCOLS + (size_t)ntile * BN + row) * KDIM + c8 * 8;
        sts[i] = (uint32_t)(row * 128 + ((c8 ^ (row & 7)) << 4));
    }

    auto issue = [&](int ch, int slot) {
        const int k0 = ch * KC;
        const uint32_t st = sbase + (uint32_t)(slot * STAGE_B);
#pragma unroll
        for (int i = 0; i < 4; i++) {
            CP_ASYNC16_Z(st + OFF_A + sts[i], ahp[i] + k0, zbA[i]);
            CP_ASYNC16(st + OFF_B + sts[i], bpp[i] + k0);
        }
        CP_COMMIT();
    };

    float acc[2][8][4];
#pragma unroll
    for (int mi = 0; mi < 2; mi++)
#pragma unroll
        for (int nj = 0; nj < 8; nj++)
#pragma unroll
            for (int q = 0; q < 4; q++) acc[mi][nj][q] = 0.f;

    // ---- ldmatrix per-lane addresses (128 B rows, mask = row&7) ----
    uint32_t aRow[2], aMsk[2];
#pragma unroll
    for (int mi = 0; mi < 2; mi++) {
        const int r = mrow0 + mi * 16 + (lid & 15);
        aRow[mi] = (uint32_t)(r * 128);
        aMsk[mi] = (uint32_t)(r & 7);
    }
    const uint32_t ja = (uint32_t)(lid >> 4);
    uint32_t bRow[4], bMsk[4];
#pragma unroll
    for (int h2 = 0; h2 < 4; h2++) {
        const int r = ncol0 + h2 * 16 + (lid & 7) + 8 * (lid >> 4);
        bRow[h2] = (uint32_t)(r * 128);
        bMsk[h2] = (uint32_t)(r & 7);
    }
    const uint32_t jb = (uint32_t)((lid >> 3) & 1);

    issue(0, 0);
    issue(1, 1);

    int slot = 0;                       // slot of chunk kc
    for (int kc = 0; kc < NCH; kc++) {
        CP_WAIT1();                     // chunk kc landed (this thread's groups)
        __syncthreads();                // makes all threads' copies visible; slot reusable
        if (kc + 2 < NCH) {
            int s2 = slot + 2;
            if (s2 >= NSTAGE) s2 -= NSTAGE;
            issue(kc + 2, s2);
        } else {
            CP_COMMIT();                // uniform group accounting
        }

        const uint32_t sa = sbase + (uint32_t)(slot * STAGE_B);
#pragma unroll
        for (int ks = 0; ks < 4; ks++) {
            uint32_t ah[2][4], bf[4][4];
#pragma unroll
            for (int mi = 0; mi < 2; mi++) {
                const uint32_t adr = sa + aRow[mi] + ((((uint32_t)(2 * ks) + ja) ^ aMsk[mi]) << 4);
                ldm_x4(ah[mi], adr + OFF_A);
            }
#pragma unroll
            for (int h2 = 0; h2 < 4; h2++) {
                const uint32_t adr = sa + bRow[h2] + ((((uint32_t)(2 * ks) + jb) ^ bMsk[h2]) << 4);
                ldm_x4(bf[h2], adr + OFF_B);
            }
#pragma unroll
            for (int mi = 0; mi < 2; mi++)
#pragma unroll
                for (int nj = 0; nj < 8; nj++) {
                    const int h2 = nj >> 1, sl = nj & 1;
                    mma16816h(acc[mi][nj], ah[mi], bf[h2][2 * sl], bf[h2][2 * sl + 1]);
                }
        }
        if (++slot == NSTAGE) slot = 0;
    }
    CP_WAIT0();

    // ---- epilogue ----
    const int lr = lid >> 2;
    const int c2 = (lid & 3) * 2;
    const float* __restrict__ bb = bias + (size_t)e * NCOLS + (size_t)ntile * BN;

#pragma unroll
    for (int mi = 0; mi < 2; mi++) {
#pragma unroll
        for (int half = 0; half < 2; half++) {
            const int rloc = mrow0 + mi * 16 + lr + half * 8;
            const int grow = row0 + rloc;
            if (grow < cnt) {
                const long long tok = idx[grow];
#pragma unroll
                for (int nj = 0; nj < 8; nj++) {
                    const int col = ncol0 + nj * 8 + c2;
                    const float v0 = acc[mi][nj][half * 2 + 0];
                    const float v1 = acc[mi][nj][half * 2 + 1];
                    if (IS_G1) {
                        float r0 = v0 + bb[col];
                        float r1 = v1 + bb[col + 1];
                        r0 = r0 > 0.f ? r0 : 0.f;
                        r1 = r1 > 0.f ? r1 : 0.f;
                        __half2 hv(__float2half_rn(r0), __float2half_rn(r1));
                        *(uint32_t*)(g_h + (size_t)tok * MID + (size_t)ntile * BN + col) =
                            *reinterpret_cast<uint32_t*>(&hv);
                    } else {
                        const size_t o = (size_t)tok * DIM + (size_t)ntile * BN + col;
                        float2 xv = *(const float2*)(x + o);
                        *(float2*)(out + o) =
                            make_float2(xv.x + v0 + bb[col], xv.y + v1 + bb[col + 1]);
                    }
                }
            }
        }
    }
}

// ---------------- host launch ----------------
extern "C" void kernel_launch(void* const* d_in, const int* in_sizes, int n_in,
                              void* d_out, int out_size) {
    const float* x       = (const float*)d_in[0];
    const void*  domains = d_in[1];
    const float* W1      = (const float*)d_in[2];
    const float* b1      = (const float*)d_in[3];
    const float* W2      = (const float*)d_in[4];
    const float* b2      = (const float*)d_in[5];
    float*       out     = (float*)d_out;

    setup_kernel<<<1, 32>>>((const int*)domains);

    __half *xh, *w1h, *w2h, *hh;
    cudaGetSymbolAddress((void**)&xh,  g_x);
    cudaGetSymbolAddress((void**)&w1h, g_w1);
    cudaGetSymbolAddress((void**)&w2h, g_w2);
    cudaGetSymbolAddress((void**)&hh,  g_h);

    prep_kernel<<<2048, 256>>>(domains, x, W1, xh, w1h);

    cudaFuncSetAttribute(moe_gemm_kernel<DIM, true>,
                         cudaFuncAttributeMaxDynamicSharedMemorySize, SMEM_TOT);
    cudaFuncSetAttribute(moe_gemm_kernel<MID, false>,
                         cudaFuncAttributeMaxDynamicSharedMemorySize, SMEM_TOT);

    // gemm1 + W2-cvt slab (blockIdx.y == 4)
    dim3 grid1(NEXP * (N_TOK / BM), MID / BN + 1);   // (256, 5)
    moe_gemm_kernel<DIM, true><<<grid1, 256, SMEM_TOT>>>(
        x, xh, w1h, b1, nullptr, W2, w2h);

    dim3 grid2(NEXP * (N_TOK / BM), DIM / BN);       // (256, 16)
    moe_gemm_kernel<MID, false><<<grid2, 256, SMEM_TOT>>>(
        x, hh, w2h, b2, out, nullptr, nullptr);
}